// round 11
// baseline (speedup 1.0000x reference)
#include <cuda_runtime.h>
#include <cuda_bf16.h>
#include <math.h>

#define BB   256
#define TT   512
#define HH   128
#define SS   4
#define DTC  0.1f

// device-global scratch (allocation-free)
__device__ float g_xproj[(size_t)BB * TT * HH];   // 64 MB, [b][t][h]
__device__ float g_hT[SS * BB * HH];

// ---- shared layout (float offsets) ----
#define OFF_WI   0            // 128*132 ROW-major [col][k], pad 132
#define OFF_V1   16896        // 32*132
#define OFF_V2   21120        // 128*36
#define OFF_BC   25728
#define OFF_V2B  25856
#define OFF_V1B  25984
#define OFF_GRP  26016
// per-group: sh 896 | sx 896 | sp 3584 | sqp 896 | sqs 224 | sred 32
#define GRP_STRIDE 6528
#define SMEM_FLOATS (OFF_GRP + 2 * GRP_STRIDE)
#define SMEM_BYTES  (SMEM_FLOATS * 4)

__device__ __forceinline__ float fast_tanh(float x) {
    float ax = fminf(fabsf(x), 12.0f);
    float e  = __expf(2.0f * ax);
    float r  = __fdividef(e - 1.0f, e + 1.0f);
    return copysignf(r, x);
}

// ---------------------------------------------------------------------------
// K1: x_proj = x @ Wp^T + bp
// ---------------------------------------------------------------------------
__global__ __launch_bounds__(128) void xproj_kernel(
    const float* __restrict__ x, const float* __restrict__ Wp,
    const float* __restrict__ bp)
{
    __shared__ float sW[128 * 36];
    __shared__ float sx[32 * 32];
    __shared__ float sb[128];
    const int tid = threadIdx.x;

    for (int idx = tid; idx < 128 * 32; idx += 128) {
        int j = idx >> 5, k = idx & 31;
        sW[j * 36 + k] = Wp[idx];
    }
    sb[tid] = bp[tid];
    const size_t base = (size_t)blockIdx.x * 32;
    for (int idx = tid; idx < 1024; idx += 128)
        sx[idx] = x[base * 32 + idx];
    __syncthreads();

    float acc[32];
    const float b = sb[tid];
    #pragma unroll
    for (int r = 0; r < 32; r++) acc[r] = b;

    #pragma unroll 2
    for (int kk = 0; kk < 32; kk += 4) {
        const float4 w4 = *(const float4*)&sW[tid * 36 + kk];
        #pragma unroll
        for (int r = 0; r < 32; r++) {
            const float4 x4 = *(const float4*)&sx[r * 32 + kk];
            acc[r] = fmaf(x4.x, w4.x, acc[r]);
            acc[r] = fmaf(x4.y, w4.y, acc[r]);
            acc[r] = fmaf(x4.z, w4.z, acc[r]);
            acc[r] = fmaf(x4.w, w4.w, acc[r]);
        }
    }
    #pragma unroll
    for (int r = 0; r < 32; r++)
        g_xproj[(base + r) * HH + tid] = acc[r];
}

// FFMA2 with k-packed operands: acc.lo/.hi accumulate even/odd k lanes.
#define FFMA2(acc, wp, xp) \
    asm("fma.rn.f32x2 %0, %1, %2, %0;" : "+l"(acc) : "l"(wp), "l"(xp))

// close a k-packed accumulator: lo + hi
__device__ __forceinline__ float pair_sum(unsigned long long a) {
    float lo, hi;
    asm("mov.b64 {%0, %1}, %2;" : "=f"(lo), "=f"(hi) : "l"(a));
    return lo + hi;
}

// ---------------------------------------------------------------------------
// k-packed partial GEMM, weights from SMEM row-major [col*132+k] (inp pass).
// Thread (w,l) owns cols 4l..4l+3 over k in [32w,32w+32) for G rows.
// ---------------------------------------------------------------------------
template<int G>
__device__ __forceinline__ void pg_ksmem(
    const float* __restrict__ sW, const float* __restrict__ svec,
    float* __restrict__ sp, int w, int l)
{
    const int k0 = 32 * w;
    const int c0 = 4 * l;
    unsigned long long a0[G], a1[G], a2[G], a3[G];
    #pragma unroll
    for (int r = 0; r < G; r++) { a0[r]=0; a1[r]=0; a2[r]=0; a3[r]=0; }

    #pragma unroll
    for (int j2 = 0; j2 < 8; j2++) {   // 4 k (=2 kpairs) per iter
        const ulonglong2 w0 = *(const ulonglong2*)&sW[(c0 + 0) * 132 + k0 + 4 * j2];
        const ulonglong2 w1 = *(const ulonglong2*)&sW[(c0 + 1) * 132 + k0 + 4 * j2];
        const ulonglong2 w2 = *(const ulonglong2*)&sW[(c0 + 2) * 132 + k0 + 4 * j2];
        const ulonglong2 w3 = *(const ulonglong2*)&sW[(c0 + 3) * 132 + k0 + 4 * j2];
        #pragma unroll
        for (int r = 0; r < G; r++) {
            const ulonglong2 xx = *(const ulonglong2*)&svec[r * 128 + k0 + 4 * j2];
            FFMA2(a0[r], w0.x, xx.x);
            FFMA2(a1[r], w1.x, xx.x);
            FFMA2(a2[r], w2.x, xx.x);
            FFMA2(a3[r], w3.x, xx.x);
            FFMA2(a0[r], w0.y, xx.y);
            FFMA2(a1[r], w1.y, xx.y);
            FFMA2(a2[r], w2.y, xx.y);
            FFMA2(a3[r], w3.y, xx.y);
        }
    }
    #pragma unroll
    for (int r = 0; r < G; r++) {
        float4 v;
        v.x = pair_sum(a0[r]);
        v.y = pair_sum(a1[r]);
        v.z = pair_sum(a2[r]);
        v.w = pair_sum(a3[r]);
        *(float4*)&sp[(r * 4 + w) * 128 + c0] = v;
    }
}

// ---------------------------------------------------------------------------
// k-packed partial GEMM with REGISTER weights (inner passes).
// wr[i*16+j] = (W[c0+i][k0+2j], W[c0+i][k0+2j+1]) packed b64.
// ---------------------------------------------------------------------------
template<int G>
__device__ __forceinline__ void pg_kreg(
    const unsigned long long* __restrict__ wr,
    const float* __restrict__ svec, float* __restrict__ sp, int w, int l)
{
    const int k0 = 32 * w;
    const int c0 = 4 * l;
    unsigned long long a0[G], a1[G], a2[G], a3[G];
    #pragma unroll
    for (int r = 0; r < G; r++) { a0[r]=0; a1[r]=0; a2[r]=0; a3[r]=0; }

    #pragma unroll
    for (int j2 = 0; j2 < 8; j2++) {
        #pragma unroll
        for (int r = 0; r < G; r++) {
            const ulonglong2 xx = *(const ulonglong2*)&svec[r * 128 + k0 + 4 * j2];
            FFMA2(a0[r], wr[0 * 16 + 2 * j2], xx.x);
            FFMA2(a1[r], wr[1 * 16 + 2 * j2], xx.x);
            FFMA2(a2[r], wr[2 * 16 + 2 * j2], xx.x);
            FFMA2(a3[r], wr[3 * 16 + 2 * j2], xx.x);
            FFMA2(a0[r], wr[0 * 16 + 2 * j2 + 1], xx.y);
            FFMA2(a1[r], wr[1 * 16 + 2 * j2 + 1], xx.y);
            FFMA2(a2[r], wr[2 * 16 + 2 * j2 + 1], xx.y);
            FFMA2(a3[r], wr[3 * 16 + 2 * j2 + 1], xx.y);
        }
    }
    #pragma unroll
    for (int r = 0; r < G; r++) {
        float4 v;
        v.x = pair_sum(a0[r]);
        v.y = pair_sum(a1[r]);
        v.z = pair_sum(a2[r]);
        v.w = pair_sum(a3[r]);
        *(float4*)&sp[(r * 4 + w) * 128 + c0] = v;
    }
}

// ---------------------------------------------------------------------------
// K2: persistent liquid recurrence. 256 threads = 2 independent 128-thread
// groups (named barriers) sharing one SMEM weight copy; Wrec in registers.
// ---------------------------------------------------------------------------
template<int G, int NS>
__device__ __forceinline__ void run_group(
    const float* __restrict__ Wrec, const float* __restrict__ tau_base,
    int s, int grow0)
{
    extern __shared__ float sm[];
    const int tid  = threadIdx.x;
    const int g    = tid >> 7;
    const int gtid = tid & 127;
    const int w = gtid >> 5, l = gtid & 31;

    float* gs   = sm + OFF_GRP + g * GRP_STRIDE;
    float* sh   = gs;
    float* sx   = gs + 896;
    float* sp   = gs + 1792;
    float* sqp  = gs + 5376;
    float* sqs  = gs + 6272;
    float* sred = gs + 6496;
    const float* sWi  = sm + OFF_WI;
    const float* sV1  = sm + OFF_V1;
    const float* sV2  = sm + OFF_V2;
    const float* sbc  = sm + OFF_BC;
    const float* sv2b = sm + OFF_V2B;
    const float* sv1b = sm + OFF_V1B;

    const int barid = g + 1;
    #define GBAR() asm volatile("bar.sync %0, 128;" :: "r"(barid) : "memory")

    // ---- Wrec slice into registers, k-packed:
    // wr[i*16+j] = (Wr[c0+i][k0+2j], Wr[c0+i][k0+2j+1])
    unsigned long long wr[64];
    {
        const float* WrS = Wrec + s * 16384;
        const int k0 = 32 * w, c0 = 4 * l;
        #pragma unroll
        for (int i = 0; i < 4; i++)
            #pragma unroll
            for (int j = 0; j < 16; j++)
                wr[i * 16 + j] =
                    *(const unsigned long long*)&WrS[(c0 + i) * 128 + k0 + 2 * j];
    }

    const float tb = tau_base[s * 128 + gtid];
    float hj[G], xreg[G];
    int xoff[G];
    #pragma unroll
    for (int r = 0; r < G; r++) {
        hj[r] = 0.f;
        sh[r * 128 + gtid] = 0.f;
        const int row = min(grow0 + r, BB - 1);
        xoff[r] = row * (TT * HH);
        xreg[r] = g_xproj[xoff[r] + gtid];
    }
    GBAR();

    for (int t = 0; t < TT; t++) {
        #pragma unroll
        for (int r = 0; r < G; r++) sx[r * 128 + gtid] = xreg[r];
        GBAR();

        // ---- gate layer 1 partials: thread l = gate row, k-chunk w ----
        {
            float qp[G];
            #pragma unroll
            for (int r = 0; r < G; r++) qp[r] = 0.f;
            const int k0 = w * 32;
            #pragma unroll
            for (int kk = 0; kk < 32; kk += 4) {
                const float4 v4 = *(const float4*)&sV1[l * 132 + k0 + kk];
                #pragma unroll
                for (int r = 0; r < G; r++) {
                    const float4 x4 = *(const float4*)&sx[r * 128 + k0 + kk];
                    qp[r] = fmaf(x4.x, v4.x, qp[r]);
                    qp[r] = fmaf(x4.y, v4.y, qp[r]);
                    qp[r] = fmaf(x4.z, v4.z, qp[r]);
                    qp[r] = fmaf(x4.w, v4.w, qp[r]);
                }
            }
            #pragma unroll
            for (int r = 0; r < G; r++) sqp[w * 224 + r * 32 + l] = qp[r];
        }
        GBAR();
        if (gtid < 32) {
            #pragma unroll
            for (int r = 0; r < G; r++) {
                float q = sqp[r * 32 + gtid] + sqp[224 + r * 32 + gtid]
                        + sqp[448 + r * 32 + gtid] + sqp[672 + r * 32 + gtid]
                        + sv1b[gtid];
                sqs[r * 32 + gtid] = fmaxf(q, 0.f);
            }
        }
        GBAR();

        // ---- gate layer 2 -> rtau (owner column gtid) ----
        float rtau[G];
        {
            float va[G];
            #pragma unroll
            for (int r = 0; r < G; r++) va[r] = sv2b[gtid];
            #pragma unroll
            for (int ii = 0; ii < 32; ii += 4) {
                const float4 w4 = *(const float4*)&sV2[gtid * 36 + ii];
                #pragma unroll
                for (int r = 0; r < G; r++) {
                    const float4 q4 = *(const float4*)&sqs[r * 32 + ii];
                    va[r] = fmaf(q4.x, w4.x, va[r]);
                    va[r] = fmaf(q4.y, w4.y, va[r]);
                    va[r] = fmaf(q4.z, w4.z, va[r]);
                    va[r] = fmaf(q4.w, w4.w, va[r]);
                }
            }
            #pragma unroll
            for (int r = 0; r < G; r++) {
                const float vol = __fdividef(1.f, 1.f + __expf(-va[r]));
                float ta = tb * (0.2f + 1.8f * (1.f - vol));
                ta = fminf(fmaxf(ta, 0.1f), 10.f);
                rtau[r] = __frcp_rn(ta);
            }
        }

        // ---- inp = x @ Wi^T + bc : k-packed smem partials then combine ----
        pg_ksmem<G>(sWi, sx, sp, w, l);
        GBAR();
        float inp[G];
        #pragma unroll
        for (int r = 0; r < G; r++)
            inp[r] = sp[(r * 4 + 0) * 128 + gtid] + sp[(r * 4 + 1) * 128 + gtid]
                   + sp[(r * 4 + 2) * 128 + gtid] + sp[(r * 4 + 3) * 128 + gtid]
                   + sbc[gtid];

        // prefetch next timestep x (L2 hit; hidden behind inner steps)
        if (t + 1 < TT) {
            #pragma unroll
            for (int r = 0; r < G; r++)
                xreg[r] = g_xproj[xoff[r] + (t + 1) * 128 + gtid];
        }
        GBAR();   // all inp-combine reads of sp done before first inner overwrite

        // ---- inner ODE steps: register-weight GEMM, 3 barriers per step ----
        #pragma unroll 1
        for (int it = 0; it < NS; it++) {
            pg_kreg<G>(wr, sh, sp, w, l);
            GBAR();

            float d[G];
            #pragma unroll
            for (int r = 0; r < G; r++) {
                const float pre = sp[(r * 4 + 0) * 128 + gtid] + sp[(r * 4 + 1) * 128 + gtid]
                                + sp[(r * 4 + 2) * 128 + gtid] + sp[(r * 4 + 3) * 128 + gtid]
                                + inp[r];
                d[r] = (fast_tanh(pre) - hj[r]) * rtau[r];
            }
            #pragma unroll
            for (int r = 0; r < G; r++) {
                float sq = d[r] * d[r];
                sq += __shfl_xor_sync(0xffffffffu, sq, 16);
                sq += __shfl_xor_sync(0xffffffffu, sq, 8);
                sq += __shfl_xor_sync(0xffffffffu, sq, 4);
                sq += __shfl_xor_sync(0xffffffffu, sq, 2);
                sq += __shfl_xor_sync(0xffffffffu, sq, 1);
                if (l == 0) sred[r * 4 + w] = sq;
            }
            GBAR();
            #pragma unroll
            for (int r = 0; r < G; r++) {
                const float4 s4 = *(const float4*)&sred[r * 4];
                const float mag = sqrtf(s4.x + s4.y + s4.z + s4.w);
                const float coef = __fdividef(DTC, 1.f + 0.2f * mag);
                hj[r] = fmaf(coef, d[r], hj[r]);
                sh[r * 128 + gtid] = hj[r];
            }
            GBAR();   // sh visible (and sp free) before next pass
        }
    }

    #pragma unroll
    for (int r = 0; r < G; r++) {
        const int row = min(grow0 + r, BB - 1);
        g_hT[(s * BB + row) * HH + gtid] = hj[r];
    }
    #undef GBAR
}

__global__ __launch_bounds__(256, 1) void liquid_kernel(
    const float* __restrict__ Wrec, const float* __restrict__ Win_w,
    const float* __restrict__ Win_b, const float* __restrict__ cbias,
    const float* __restrict__ tau_base,
    const float* __restrict__ v1w, const float* __restrict__ v1b,
    const float* __restrict__ v2w, const float* __restrict__ v2b)
{
    extern __shared__ float sm[];
    const int tid = threadIdx.x;
    const int b = blockIdx.x;

    int s, row0;
    if      (b < 21) { s = 0; row0 = b * 13; }
    else if (b < 53) { s = 1; row0 = (b - 21) * 8; }
    else if (b < 96) { s = 2; row0 = (b - 53) * 6; }
    else             { s = 3; row0 = (b - 96) * 5; }

    // stage Win ROW-major padded: sWi[col*132 + k]
    const float* Wi = Win_w + s * 16384;
    for (int idx = tid; idx < 16384; idx += 256) {
        const int j = idx >> 7, k = idx & 127;
        sm[OFF_WI + j * 132 + k] = Wi[idx];
    }
    for (int idx = tid; idx < 32 * 128; idx += 256) {
        int j = idx >> 7, k = idx & 127;
        sm[OFF_V1 + j * 132 + k] = v1w[s * 4096 + idx];
    }
    for (int idx = tid; idx < 128 * 32; idx += 256) {
        int j = idx >> 5, k = idx & 31;
        sm[OFF_V2 + j * 36 + k] = v2w[s * 4096 + idx];
    }
    if (tid < 128) {
        sm[OFF_BC  + tid] = Win_b[s * 128 + tid] + cbias[s * 128 + tid];
        sm[OFF_V2B + tid] = v2b[s * 128 + tid];
        if (tid < 32) sm[OFF_V1B + tid] = v1b[s * 32 + tid];
    }
    __syncthreads();

    const int g = tid >> 7;
    if      (b < 21) { if (!g) run_group<7, 3>(Wrec, tau_base, 0, row0);
                       else    run_group<6, 3>(Wrec, tau_base, 0, row0 + 7); }
    else if (b < 53) {          run_group<4, 5>(Wrec, tau_base, 1, row0 + g * 4); }
    else if (b < 96) {          run_group<3, 7>(Wrec, tau_base, 2, row0 + g * 3); }
    else             { if (!g) run_group<3, 9>(Wrec, tau_base, 3, row0);
                       else    run_group<2, 9>(Wrec, tau_base, 3, row0 + 3); }
}

// ---------------------------------------------------------------------------
// K3: projection + concat + fusion MLP. One block per batch row.
// ---------------------------------------------------------------------------
__global__ __launch_bounds__(128) void head_kernel(
    const float* __restrict__ proj_w, const float* __restrict__ proj_b,
    const float* __restrict__ f1w, const float* __restrict__ f1b,
    const float* __restrict__ f2w, const float* __restrict__ f2b,
    const float* __restrict__ f3w, const float* __restrict__ f3b,
    float* __restrict__ out)
{
    __shared__ float fused[128];
    __shared__ float h1[128];
    __shared__ float h2[64];
    __shared__ float part[2];
    const int b = blockIdx.x;
    const int j = threadIdx.x;
    const int s = j >> 5, i = j & 31;

    {
        const float* h  = &g_hT[(s * BB + b) * HH];
        const float* pw = &proj_w[(s * 32 + i) * HH];
        float a = proj_b[s * 32 + i];
        #pragma unroll 8
        for (int k = 0; k < 128; k++) a = fmaf(h[k], pw[k], a);
        fused[j] = a;
    }
    __syncthreads();
    {
        float a = f1b[j];
        const float* wrow = &f1w[j * 128];
        #pragma unroll 8
        for (int k = 0; k < 128; k++) a = fmaf(fused[k], wrow[k], a);
        h1[j] = fmaxf(a, 0.f);
    }
    __syncthreads();
    if (j < 64) {
        float a = f2b[j];
        const float* wrow = &f2w[j * 128];
        #pragma unroll 8
        for (int k = 0; k < 128; k++) a = fmaf(h1[k], wrow[k], a);
        h2[j] = fmaxf(a, 0.f);
    }
    __syncthreads();
    if (j < 64) {
        float p = h2[j] * f3w[j];
        p += __shfl_xor_sync(0xffffffffu, p, 16);
        p += __shfl_xor_sync(0xffffffffu, p, 8);
        p += __shfl_xor_sync(0xffffffffu, p, 4);
        p += __shfl_xor_sync(0xffffffffu, p, 2);
        p += __shfl_xor_sync(0xffffffffu, p, 1);
        if ((j & 31) == 0) part[j >> 5] = p;
    }
    __syncthreads();
    if (j == 0) out[b] = part[0] + part[1] + f3b[0];
}

// ---------------------------------------------------------------------------
extern "C" void kernel_launch(void* const* d_in, const int* in_sizes, int n_in,
                              void* d_out, int out_size)
{
    const float* x        = (const float*)d_in[0];
    const float* Wp       = (const float*)d_in[1];
    const float* bp       = (const float*)d_in[2];
    const float* Wrec     = (const float*)d_in[3];
    const float* Win_w    = (const float*)d_in[4];
    const float* Win_b    = (const float*)d_in[5];
    const float* cbias    = (const float*)d_in[6];
    const float* tau_base = (const float*)d_in[7];
    const float* vg1_w    = (const float*)d_in[8];
    const float* vg1_b    = (const float*)d_in[9];
    const float* vg2_w    = (const float*)d_in[10];
    const float* vg2_b    = (const float*)d_in[11];
    const float* proj_w   = (const float*)d_in[12];
    const float* proj_b   = (const float*)d_in[13];
    const float* f1w      = (const float*)d_in[14];
    const float* f1b      = (const float*)d_in[15];
    const float* f2w      = (const float*)d_in[16];
    const float* f2b      = (const float*)d_in[17];
    const float* f3w      = (const float*)d_in[18];
    const float* f3b      = (const float*)d_in[19];
    float* out = (float*)d_out;

    cudaFuncSetAttribute(liquid_kernel,
                         cudaFuncAttributeMaxDynamicSharedMemorySize, SMEM_BYTES);

    xproj_kernel<<<(BB * TT) / 32, 128>>>(x, Wp, bp);
    liquid_kernel<<<148, 256, SMEM_BYTES>>>(Wrec, Win_w, Win_b, cbias, tau_base,
                                            vg1_w, vg1_b, vg2_w, vg2_b);
    head_kernel<<<BB, 128>>>(proj_w, proj_b, f1w, f1b, f2w, f2b, f3w, f3b, out);
}